// round 1
// baseline (speedup 1.0000x reference)
#include <cuda_runtime.h>
#include <cstdint>

#define Bsz 512
#define Nn  8192

// Scratch ([i][b] layouts for coalesced scan access; static __device__ per harness rules)
__device__ float2 g_lplq[(size_t)Bsz * Nn];   // (lp_i, lq_i) transposed [i][b]
__device__ float  g_uT  [(size_t)Bsz * Nn];   // noise transposed [i][b]
__device__ float2 g_xa  [(size_t)Bsz * Nn];   // (x1_i = A0_{i-1}+lp_i, A1_i) [i][b]
__device__ int    g_sel [Bsz];

__device__ __forceinline__ float neg_inf_f() { return __int_as_float(0xff800000); }

// log1mexp(x) = log(1 - e^x), x <= 0, matching the reference's branch structure
__device__ __forceinline__ float log1mexp_f(float x) {
    return (x > -0.69314718f) ? logf(-expm1f(x)) : log1pf(-expf(x));
}

// ---------------------------------------------------------------------------
// Kernel 1: elementwise lp/lq from logits, transpose lp/lq and noise to [i][b]
// ---------------------------------------------------------------------------
__global__ void k_prep(const float* __restrict__ logits,
                       const float* __restrict__ noise) {
    __shared__ float2 tile[32][33];
    __shared__ float  tu  [32][33];
    const int tx = threadIdx.x, ty = threadIdx.y;
    const int i0 = blockIdx.x * 32;   // item index base
    const int b0 = blockIdx.y * 32;   // row index base

    #pragma unroll
    for (int r = 0; r < 4; r++) {
        const int b = b0 + ty + r * 8;
        const int i = i0 + tx;
        const size_t src = (size_t)b * Nn + i;
        const float z = logits[src];
        // jax.nn.log_sigmoid(z) = -(max(-z,0) + log1p(exp(-|z|)))
        const float sp = fmaxf(-z, 0.0f) + log1pf(expf(-fabsf(z)));
        const float lp = fminf(-sp, -1e-7f);
        const float lq = log1mexp_f(lp);
        tile[ty + r * 8][tx] = make_float2(lp, lq);
        tu  [ty + r * 8][tx] = noise[src];
    }
    __syncthreads();
    #pragma unroll
    for (int r = 0; r < 4; r++) {
        const int i = i0 + ty + r * 8;
        const int b = b0 + tx;
        const size_t dst = (size_t)i * Bsz + b;
        g_lplq[dst] = tile[tx][ty + r * 8];
        g_uT[dst]   = tu  [tx][ty + r * 8];
    }
    // reset per-row selection (graph replays must be deterministic)
    if (blockIdx.x == 0 && blockIdx.y < 2) {
        const int t = ty * 32 + tx;  // 0..255
        g_sel[blockIdx.y * 256 + t] = -1;
    }
}

// ---------------------------------------------------------------------------
// Kernel 2: sequential forward DP per row (the irreducible latency chain).
// A0' = A0 + lq  (exactly what logaddexp_c gives with a -inf arm)
// A1' = max(x1,x2) + log1p(exp(-|x1-x2|)), x1 = A0+lp, x2 = A1+lq
// Emits (x1_i, A1_i) so the reverse pass becomes fully parallel.
// ---------------------------------------------------------------------------
__global__ void __launch_bounds__(32, 1) k_scan() {
    const int b = blockIdx.x * 32 + threadIdx.x;
    float A0 = 0.0f;
    float A1 = neg_inf_f();

    constexpr int CH = 16;
    constexpr int NC = Nn / CH;
    float2 bufA[CH], bufB[CH];

    #pragma unroll
    for (int j = 0; j < CH; j++) bufA[j] = g_lplq[(size_t)j * Bsz + b];
    #pragma unroll
    for (int j = 0; j < CH; j++) bufB[j] = g_lplq[(size_t)(CH + j) * Bsz + b];

    for (int c = 0; c < NC; c += 2) {
        #pragma unroll
        for (int j = 0; j < CH; j++) {
            const float lp = bufA[j].x, lq = bufA[j].y;
            const float x1 = A0 + lp;
            const float x2 = A1 + lq;
            const float m  = fmaxf(x1, x2);
            const float dd = x1 - x2;               // +inf when A1 = -inf (step 1): exp->0, ok
            const float t  = log1pf(expf(-fabsf(dd)));
            A1 = m + t;
            A0 = A0 + lq;
            g_xa[(size_t)(c * CH + j) * Bsz + b] = make_float2(x1, A1);
        }
        if (c + 2 < NC) {
            #pragma unroll
            for (int j = 0; j < CH; j++)
                bufA[j] = g_lplq[(size_t)((c + 2) * CH + j) * Bsz + b];
        }
        #pragma unroll
        for (int j = 0; j < CH; j++) {
            const float lp = bufB[j].x, lq = bufB[j].y;
            const float x1 = A0 + lp;
            const float x2 = A1 + lq;
            const float m  = fmaxf(x1, x2);
            const float dd = x1 - x2;
            const float t  = log1pf(expf(-fabsf(dd)));
            A1 = m + t;
            A0 = A0 + lq;
            g_xa[(size_t)((c + 1) * CH + j) * Bsz + b] = make_float2(x1, A1);
        }
        if (c + 3 < NC) {
            #pragma unroll
            for (int j = 0; j < CH; j++)
                bufB[j] = g_lplq[(size_t)((c + 3) * CH + j) * Bsz + b];
        }
    }
}

// ---------------------------------------------------------------------------
// Kernel 3: parallel reverse-pass decisions. With K=1, j stays at its initial
// value until the single success, so the selected item is simply the MAX index
// i with u_i < sigmoid(p_i - q_i). Thresholds after the success are exactly 0.
// ---------------------------------------------------------------------------
__global__ void k_decide() {
    const int e = blockIdx.x * blockDim.x + threadIdx.x;  // e = i*Bsz + b
    const int b = e & (Bsz - 1);
    const int i = e >> 9;
    const float2 xa = g_xa[e];
    float r = xa.x - xa.y;            // (A0_{i-1} + lp_i) - A1_i, reference op order
    r = fminf(r, 0.0f);
    const float q = log1mexp_f(r);
    const float d = r - q;
    const float t = 1.0f / (1.0f + expf(-d));  // sigmoid; d=+inf -> t=1, d=-inf -> t=0
    const float u = g_uT[e];
    if (u < t) atomicMax(&g_sel[b], i);
}

// ---------------------------------------------------------------------------
// Kernel 4: write output (one 1 per row at the selected index, else 0)
// ---------------------------------------------------------------------------
__global__ void k_write(float* __restrict__ out) {
    const int e = blockIdx.x * blockDim.x + threadIdx.x;  // e = b*Nn + i
    const int b = e >> 13;
    const int i = e & (Nn - 1);
    out[e] = (i == g_sel[b]) ? 1.0f : 0.0f;
}

extern "C" void kernel_launch(void* const* d_in, const int* in_sizes, int n_in,
                              void* d_out, int out_size) {
    const float* logits = (const float*)d_in[0];
    const float* noise  = (const float*)d_in[1];
    float* out = (float*)d_out;

    dim3 b1(32, 8), g1(Nn / 32, Bsz / 32);
    k_prep<<<g1, b1>>>(logits, noise);
    k_scan<<<Bsz / 32, 32>>>();
    k_decide<<<(Bsz * Nn) / 256, 256>>>();
    k_write<<<(Bsz * Nn) / 256, 256>>>(out);
}